// round 7
// baseline (speedup 1.0000x reference)
#include <cuda_runtime.h>
#include <cstdint>

// HitTheMiddleModel: per-row physics + 1e-10 * (x @ W^T + b).
// B = 8388608 rows x 3 fp32 in/out. Steady-state replay loop is pinned by
// per-replay DRAM traffic (201MB @ ~5.67TB/s sustained = 35.3us).
// R6: fractional L2 policy on the x read stream. R5 showed full-footprint
// evict_last (100MB sticky > L2 retention capacity) self-thrashes and gains
// ~1%. createpolicy.fractional with frac=0.55 marks only ~55MB of x lines
// evict_last (rest evict_first) -> sticky set fits stably in 126MB L2
// alongside the evict_first write sweep -> ~55MB of reads become L2 hits
// per replay -> per-replay DRAM ~145MB.
// Keeps R3 geometry: 8 rows/thread = 96B = 3x v8.b32, 256-bit ld/st.

#define B_ROWS 8388608
#define ROWS_PER_THREAD 8
#define THREADS_PER_BLOCK 256

__device__ __forceinline__ uint64_t make_frac_policy() {
    uint64_t pol;
    asm("createpolicy.fractional.L2::evict_last.L2::evict_first.b64 %0, 0.55;"
        : "=l"(pol));
    return pol;
}

__device__ __forceinline__ void ldg256_pol(const float* p, uint32_t* r, uint64_t pol) {
    asm volatile(
        "ld.global.nc.L2::cache_hint.v8.b32 {%0,%1,%2,%3,%4,%5,%6,%7}, [%8], %9;"
        : "=r"(r[0]), "=r"(r[1]), "=r"(r[2]), "=r"(r[3]),
          "=r"(r[4]), "=r"(r[5]), "=r"(r[6]), "=r"(r[7])
        : "l"(p), "l"(pol));
}

__device__ __forceinline__ void stg256_drain(float* p, const uint32_t* r) {
    asm volatile(
        "st.global.L2::evict_first.v8.b32 [%0], {%1,%2,%3,%4,%5,%6,%7,%8};"
        :: "l"(p),
           "r"(r[0]), "r"(r[1]), "r"(r[2]), "r"(r[3]),
           "r"(r[4]), "r"(r[5]), "r"(r[6]), "r"(r[7])
        : "memory");
}

__device__ __forceinline__ void row_compute(
    float x0, float x1, float x2,
    const float* w, float b0, float b1, float b2,
    float& o0, float& o1, float& o2)
{
    float vel = x1 + x2;
    float pos = x0 + vel;
    bool hit = (pos > 10.0f) || (pos < -10.0f);
    vel = hit ? -vel : vel;
    pos = fminf(fmaxf(pos, -10.0f), 10.0f);
    float reward = -pos * pos;

    float y0 = fmaf(x0, w[0], fmaf(x1, w[1], fmaf(x2, w[2], b0)));
    float y1 = fmaf(x0, w[3], fmaf(x1, w[4], fmaf(x2, w[5], b1)));
    float y2 = fmaf(x0, w[6], fmaf(x1, w[7], fmaf(x2, w[8], b2)));

    o0 = fmaf(1e-10f, y0, pos);
    o1 = fmaf(1e-10f, y1, vel);
    o2 = fmaf(1e-10f, y2, reward);
}

__global__ void __launch_bounds__(THREADS_PER_BLOCK)
hit_middle_kernel(const float* __restrict__ x,
                  const float* __restrict__ W,
                  const float* __restrict__ bb,
                  float* __restrict__ out)
{
    const unsigned t = blockIdx.x * THREADS_PER_BLOCK + threadIdx.x;
    const uint64_t pol = make_frac_policy();

    // Broadcast loads (tiny, L1-resident).
    float w[9];
#pragma unroll
    for (int i = 0; i < 9; i++) w[i] = W[i];
    const float b0 = bb[0], b1 = bb[1], b2 = bb[2];

    // 8 rows = 24 floats = 96B per thread = 3x 256-bit, all 32B-aligned.
    const unsigned base = 24u * t;

    uint32_t u[24];
#pragma unroll
    for (int i = 0; i < 3; i++) ldg256_pol(x + base + 8u * i, u + 8 * i, pol);

    uint32_t o[24];
#pragma unroll
    for (int r = 0; r < ROWS_PER_THREAD; r++) {
        float r0, r1, r2;
        row_compute(__uint_as_float(u[3*r]),
                    __uint_as_float(u[3*r+1]),
                    __uint_as_float(u[3*r+2]),
                    w, b0, b1, b2, r0, r1, r2);
        o[3*r]   = __float_as_uint(r0);
        o[3*r+1] = __float_as_uint(r1);
        o[3*r+2] = __float_as_uint(r2);
    }

#pragma unroll
    for (int i = 0; i < 3; i++) stg256_drain(out + base + 8u * i, o + 8 * i);
}

extern "C" void kernel_launch(void* const* d_in, const int* in_sizes, int n_in,
                              void* d_out, int out_size)
{
    const float* x  = (const float*)d_in[0];   // x [B,3] fp32
    const float* W  = (const float*)d_in[1];   // W [3,3]
    const float* bb = (const float*)d_in[2];   // b [3]
    float* out = (float*)d_out;                // [B,3] fp32

    const int total_threads = B_ROWS / ROWS_PER_THREAD;      // 1048576
    const int blocks = total_threads / THREADS_PER_BLOCK;    // 4096

    hit_middle_kernel<<<blocks, THREADS_PER_BLOCK>>>(x, W, bb, out);
}

// round 8
// speedup vs baseline: 1.1151x; 1.1151x over previous
#include <cuda_runtime.h>
#include <cstdint>

// HitTheMiddleModel: per-row physics + 1e-10 * (x @ W^T + b).
// B = 8388608 rows x 3 fp32 in/out. Established by R1-R6: per-replay DRAM
// traffic is irreducibly 201MB (all L2 cross-replay retention schemes lose);
// sustained HBM ~5.7TB/s -> floor ~34.5-35us.
// R7: keep only the demonstrably-helpful hint: evict_first on the store
// stream (output never re-read; demote so it can't pollute L2 for the
// in-flight read stream). Plain .nc v8 reads (sticky read hint was neutral
// at best, R6 fractional regressed). 512-thread blocks for tail behavior.
// 8 rows/thread = 96B = 3x 256-bit ld/st, all 32B-aligned, fully coalesced.

#define B_ROWS 8388608
#define ROWS_PER_THREAD 8
#define THREADS_PER_BLOCK 512

__device__ __forceinline__ void ldg256(const float* p, uint32_t* r) {
    asm volatile(
        "ld.global.nc.v8.b32 {%0,%1,%2,%3,%4,%5,%6,%7}, [%8];"
        : "=r"(r[0]), "=r"(r[1]), "=r"(r[2]), "=r"(r[3]),
          "=r"(r[4]), "=r"(r[5]), "=r"(r[6]), "=r"(r[7])
        : "l"(p));
}

__device__ __forceinline__ void stg256_drain(float* p, const uint32_t* r) {
    asm volatile(
        "st.global.L2::evict_first.v8.b32 [%0], {%1,%2,%3,%4,%5,%6,%7,%8};"
        :: "l"(p),
           "r"(r[0]), "r"(r[1]), "r"(r[2]), "r"(r[3]),
           "r"(r[4]), "r"(r[5]), "r"(r[6]), "r"(r[7])
        : "memory");
}

__device__ __forceinline__ void row_compute(
    float x0, float x1, float x2,
    const float* w, float b0, float b1, float b2,
    float& o0, float& o1, float& o2)
{
    float vel = x1 + x2;
    float pos = x0 + vel;
    bool hit = (pos > 10.0f) || (pos < -10.0f);
    vel = hit ? -vel : vel;
    pos = fminf(fmaxf(pos, -10.0f), 10.0f);
    float reward = -pos * pos;

    float y0 = fmaf(x0, w[0], fmaf(x1, w[1], fmaf(x2, w[2], b0)));
    float y1 = fmaf(x0, w[3], fmaf(x1, w[4], fmaf(x2, w[5], b1)));
    float y2 = fmaf(x0, w[6], fmaf(x1, w[7], fmaf(x2, w[8], b2)));

    o0 = fmaf(1e-10f, y0, pos);
    o1 = fmaf(1e-10f, y1, vel);
    o2 = fmaf(1e-10f, y2, reward);
}

__global__ void __launch_bounds__(THREADS_PER_BLOCK)
hit_middle_kernel(const float* __restrict__ x,
                  const float* __restrict__ W,
                  const float* __restrict__ bb,
                  float* __restrict__ out)
{
    const unsigned t = blockIdx.x * THREADS_PER_BLOCK + threadIdx.x;

    // Broadcast loads (tiny, L1-resident).
    float w[9];
#pragma unroll
    for (int i = 0; i < 9; i++) w[i] = W[i];
    const float b0 = bb[0], b1 = bb[1], b2 = bb[2];

    // 8 rows = 24 floats = 96B per thread = 3x 256-bit, all 32B-aligned.
    const unsigned base = 24u * t;

    uint32_t u[24];
#pragma unroll
    for (int i = 0; i < 3; i++) ldg256(x + base + 8u * i, u + 8 * i);

    uint32_t o[24];
#pragma unroll
    for (int r = 0; r < ROWS_PER_THREAD; r++) {
        float r0, r1, r2;
        row_compute(__uint_as_float(u[3*r]),
                    __uint_as_float(u[3*r+1]),
                    __uint_as_float(u[3*r+2]),
                    w, b0, b1, b2, r0, r1, r2);
        o[3*r]   = __float_as_uint(r0);
        o[3*r+1] = __float_as_uint(r1);
        o[3*r+2] = __float_as_uint(r2);
    }

#pragma unroll
    for (int i = 0; i < 3; i++) stg256_drain(out + base + 8u * i, o + 8 * i);
}

extern "C" void kernel_launch(void* const* d_in, const int* in_sizes, int n_in,
                              void* d_out, int out_size)
{
    const float* x  = (const float*)d_in[0];   // x [B,3] fp32
    const float* W  = (const float*)d_in[1];   // W [3,3]
    const float* bb = (const float*)d_in[2];   // b [3]
    float* out = (float*)d_out;                // [B,3] fp32

    const int total_threads = B_ROWS / ROWS_PER_THREAD;      // 1048576
    const int blocks = total_threads / THREADS_PER_BLOCK;    // 2048

    hit_middle_kernel<<<blocks, THREADS_PER_BLOCK>>>(x, W, bb, out);
}

// round 9
// speedup vs baseline: 1.1439x; 1.0258x over previous
#include <cuda_runtime.h>
#include <cstdint>

// HitTheMiddleModel: per-row physics + 1e-10 * (x @ W^T + b).
// B = 8388608 rows x 3 fp32 in/out.
// FINAL CONFIG (= R5, re-benched for reproducibility per rigor.md):
//   - 8 rows/thread = 96B = 3x 256-bit ld/st (LDG.E.256/STG.E.256),
//     all 32B-aligned, fully coalesced, MLP_p1=3.
//   - ld.global.nc.L2::evict_last on the x read stream (best measured:
//     35.04us vs 35.5-35.6 for all other hint combos).
//   - st.global.L2::evict_first on the output stream (never re-read;
//     demote so stores can't displace the read stream).
//   - 256 threads x 4096 blocks.
// Ledger: plain(R1) 35.52 | v8(R3) 35.55 | this(R5) 35.04 | st-only(R7)
// 35.58 | .cs(R2) 43.8 | st-sticky(R4) 47.9 | fractional(R6) 39.7.
// Replay loop is pinned at 201MB/replay over ~5.7TB/s sustained HBM.

#define B_ROWS 8388608
#define ROWS_PER_THREAD 8
#define THREADS_PER_BLOCK 256

__device__ __forceinline__ void ldg256_keep(const float* p, uint32_t* r) {
    asm volatile(
        "ld.global.nc.L2::evict_last.v8.b32 {%0,%1,%2,%3,%4,%5,%6,%7}, [%8];"
        : "=r"(r[0]), "=r"(r[1]), "=r"(r[2]), "=r"(r[3]),
          "=r"(r[4]), "=r"(r[5]), "=r"(r[6]), "=r"(r[7])
        : "l"(p));
}

__device__ __forceinline__ void stg256_drain(float* p, const uint32_t* r) {
    asm volatile(
        "st.global.L2::evict_first.v8.b32 [%0], {%1,%2,%3,%4,%5,%6,%7,%8};"
        :: "l"(p),
           "r"(r[0]), "r"(r[1]), "r"(r[2]), "r"(r[3]),
           "r"(r[4]), "r"(r[5]), "r"(r[6]), "r"(r[7])
        : "memory");
}

__device__ __forceinline__ void row_compute(
    float x0, float x1, float x2,
    const float* w, float b0, float b1, float b2,
    float& o0, float& o1, float& o2)
{
    float vel = x1 + x2;
    float pos = x0 + vel;
    bool hit = (pos > 10.0f) || (pos < -10.0f);
    vel = hit ? -vel : vel;
    pos = fminf(fmaxf(pos, -10.0f), 10.0f);
    float reward = -pos * pos;

    float y0 = fmaf(x0, w[0], fmaf(x1, w[1], fmaf(x2, w[2], b0)));
    float y1 = fmaf(x0, w[3], fmaf(x1, w[4], fmaf(x2, w[5], b1)));
    float y2 = fmaf(x0, w[6], fmaf(x1, w[7], fmaf(x2, w[8], b2)));

    o0 = fmaf(1e-10f, y0, pos);
    o1 = fmaf(1e-10f, y1, vel);
    o2 = fmaf(1e-10f, y2, reward);
}

__global__ void __launch_bounds__(THREADS_PER_BLOCK)
hit_middle_kernel(const float* __restrict__ x,
                  const float* __restrict__ W,
                  const float* __restrict__ bb,
                  float* __restrict__ out)
{
    const unsigned t = blockIdx.x * THREADS_PER_BLOCK + threadIdx.x;

    // Broadcast loads (tiny, L1-resident).
    float w[9];
#pragma unroll
    for (int i = 0; i < 9; i++) w[i] = W[i];
    const float b0 = bb[0], b1 = bb[1], b2 = bb[2];

    // 8 rows = 24 floats = 96B per thread = 3x 256-bit, all 32B-aligned.
    const unsigned base = 24u * t;

    uint32_t u[24];
#pragma unroll
    for (int i = 0; i < 3; i++) ldg256_keep(x + base + 8u * i, u + 8 * i);

    uint32_t o[24];
#pragma unroll
    for (int r = 0; r < ROWS_PER_THREAD; r++) {
        float r0, r1, r2;
        row_compute(__uint_as_float(u[3*r]),
                    __uint_as_float(u[3*r+1]),
                    __uint_as_float(u[3*r+2]),
                    w, b0, b1, b2, r0, r1, r2);
        o[3*r]   = __float_as_uint(r0);
        o[3*r+1] = __float_as_uint(r1);
        o[3*r+2] = __float_as_uint(r2);
    }

#pragma unroll
    for (int i = 0; i < 3; i++) stg256_drain(out + base + 8u * i, o + 8 * i);
}

extern "C" void kernel_launch(void* const* d_in, const int* in_sizes, int n_in,
                              void* d_out, int out_size)
{
    const float* x  = (const float*)d_in[0];   // x [B,3] fp32
    const float* W  = (const float*)d_in[1];   // W [3,3]
    const float* bb = (const float*)d_in[2];   // b [3]
    float* out = (float*)d_out;                // [B,3] fp32

    const int total_threads = B_ROWS / ROWS_PER_THREAD;      // 1048576
    const int blocks = total_threads / THREADS_PER_BLOCK;    // 4096

    hit_middle_kernel<<<blocks, THREADS_PER_BLOCK>>>(x, W, bb, out);
}